// round 3
// baseline (speedup 1.0000x reference)
#include <cuda_runtime.h>
#include <cstddef>

#define NF 1025      // n_stft
#define NFP 1028     // padded spec row stride (floats)
#define NG4 257      // float4 granules per spec row
#define NM 128       // n_mels
#define NB 4         // batch
#define TT 1024      // time
#define ROWS 8       // (b,t) rows per CTA
#define NTHREADS 256
#define ITERS 20
#define NBLOCKS ((NB * TT) / ROWS)   // 512
#define CG 7         // granules per gather chunk
#define NCH 256      // chunk slots (real <= 237, rest dummy)
#define DUMMY 255    // guaranteed-zero partial slot

__device__ float  g_w0[NF];
__device__ float  g_w1[NF];
__device__ int    g_mi[NF];
__device__ int    g_cmeta[NCH];     // g0 | ngc<<9
__device__ int    g_mmeta[NM];      // cstart | ccount<<16
__device__ float4 g_wg[NCH * CG];   // per-chunk weight granules (zero-padded)

// ---------------------------------------------------------------------------
// Fused prep: sparse structure + balanced chunk schedule + weight windows.
// Single block; all cross-thread state in shared, one __syncthreads per stage.
// ---------------------------------------------------------------------------
__global__ void prep_all(const float* __restrict__ fb) {
    __shared__ int s_fs[NM], s_fe[NM];
    __shared__ int s_a4[NM], s_ng[NM], s_cs[NM];
    __shared__ int s_cmel[NCH];
    __shared__ int s_nchunk;
    const int t = threadIdx.x;

    if (t < NM) { s_fs[t] = NF; s_fe[t] = 0; }
    __syncthreads();

    // per-freq: first nonzero mel + its two weights
    for (int f = t; f < NF; f += NTHREADS) {
        const float* row = fb + (size_t)f * NM;
        int mi = -1;
        for (int m = 0; m < NM; m++) if (row[m] > 0.0f) { mi = m; break; }
        float w0 = 0.0f, w1 = 0.0f;
        if (mi >= 0) {
            w0 = row[mi];
            w1 = (mi + 1 < NM) ? row[mi + 1] : 0.0f;
        } else mi = 0;
        g_mi[f] = mi; g_w0[f] = w0; g_w1[f] = w1;
        if (w0 > 0.0f) { atomicMin(&s_fs[mi], f); atomicMax(&s_fe[mi], f + 1); }
        if (w1 > 0.0f) { atomicMin(&s_fs[mi + 1], f); atomicMax(&s_fe[mi + 1], f + 1); }
    }
    __syncthreads();

    // per-mel granule span
    if (t < NM) {
        int fs = s_fs[t], fe = s_fe[t];
        int a4 = 0, ng = 0;
        if (fe > fs) { a4 = fs >> 2; ng = ((fe + 3) >> 2) - a4; }
        s_a4[t] = a4; s_ng[t] = ng;
    }
    __syncthreads();

    // serial prefix over 128 mels (trivial)
    if (t == 0) {
        int acc = 0;
        for (int m = 0; m < NM; m++) {
            s_cs[m] = acc;
            acc += (s_ng[m] + CG - 1) / CG;
        }
        s_nchunk = acc;    // bound: <= 768/7 + 128 = 237
    }
    __syncthreads();

    const int nchunk = s_nchunk;
    if (t < NM) {
        int cc = (s_ng[t] + CG - 1) / CG;
        g_mmeta[t] = s_cs[t] | (cc << 16);
        for (int k = 0; k < cc; k++) {
            int c = s_cs[t] + k;
            int ngc = s_ng[t] - k * CG; if (ngc > CG) ngc = CG;
            g_cmeta[c] = (s_a4[t] + k * CG) | (ngc << 9);
            s_cmel[c] = t;
        }
    }
    __syncthreads();
    for (int c = nchunk + t; c < NCH; c += NTHREADS) {
        g_cmeta[c] = 0;          // ngc = 0 -> zero partial every iter
        s_cmel[c] = -1;
    }
    __syncthreads();

    // weight windows: exact fb values (zeros outside NF / pad slots)
    for (int i = t; i < NCH * CG; i += NTHREADS) {
        int c = i / CG, j = i % CG;
        float4 w = make_float4(0.f, 0.f, 0.f, 0.f);
        int m = s_cmel[c];
        if (m >= 0) {
            int cm = g_cmeta[c];
            int g0 = cm & 511, ngc = (cm >> 9) & 15;
            if (j < ngc) {
                int fbase = (g0 + j) * 4;
                float v[4];
#pragma unroll
                for (int e = 0; e < 4; e++) {
                    int f = fbase + e;
                    v[e] = (f < NF) ? fb[(size_t)f * NM + m] : 0.0f;
                }
                w = make_float4(v[0], v[1], v[2], v[3]);
            }
        }
        g_wg[i] = w;
    }
}

// ---------------------------------------------------------------------------
// Main: 20-iteration SGD for 8 independent (b,t) rows per CTA.
// smem = spec(8x1028f) + partials(256x2 float4) + diff_t(129x8f) + mel_t(128x8f)
//      = 49312 B -> occupancy 4 (single wave of 512 CTAs)
// ---------------------------------------------------------------------------
__global__ __launch_bounds__(NTHREADS, 4)
void invmel_main(const float* __restrict__ melspec,
                 const float* __restrict__ spec_init,
                 float* __restrict__ out) {
    extern __shared__ float sm[];
    float*  s_spec = sm;                                  // ROWS*NFP
    float4* s_part = (float4*)(s_spec + ROWS * NFP);      // NCH*2
    float*  s_dt   = (float*)(s_part + NCH * 2);          // 129*8 (diff transposed)
    float*  s_mel  = s_dt + 129 * 8;                      // 128*8 (mel transposed)

    const float c_LR  = 0.3f;
    const float c_MOM = 0.9f;
    const float c_INV = 2.0f / (float)(NB * TT);

    const int tid  = threadIdx.x;
    const int row0 = blockIdx.x * ROWS;
    const int b    = row0 / TT;
    const int t0   = row0 % TT;
    const int m    = tid & (NM - 1);
    const int rg   = tid >> 7;

    // ---- stage spec + mel into shared ----
    for (int r = 0; r < ROWS; r++)
        for (int f = tid; f < NFP; f += NTHREADS)
            s_spec[r * NFP + f] = (f < NF) ? spec_init[(size_t)(row0 + r) * NF + f] : 0.0f;
    for (int i = tid; i < NM * ROWS; i += NTHREADS) {
        int mm = i >> 3, r = i & 7;
        s_mel[mm * 8 + r] = melspec[((size_t)b * NM + mm) * TT + t0 + r];
    }
    for (int i = tid; i < 129 * 8; i += NTHREADS) s_dt[i] = 0.0f;

    // ---- per-thread gather chunk (uniform: one chunk x 8 rows) ----
    const int cm  = g_cmeta[tid];
    const int g0  = cm & 511;
    const int ngc = (cm >> 9) & 15;
    const float4* wg = g_wg + tid * CG;

    // ---- per-(mel,rowgroup) combine slots ----
    const int mm0 = g_mmeta[m];
    const int cs  = mm0 & 0xFFFF, cc = mm0 >> 16;
    const int c0  = ((cc >= 1) ? cs     : DUMMY) * 2 + rg;
    const int c1  = ((cc >= 2) ? cs + 1 : DUMMY) * 2 + rg;

    // ---- phase-3 ownership: f = k*256 + tid ----
    float w0r[4], w1r[4];
    int   mir[4];
    float rb[4][ROWS];
#pragma unroll
    for (int k = 0; k < 4; k++) {
        int f = k * NTHREADS + tid;
        w0r[k] = g_w0[f]; w1r[k] = g_w1[f]; mir[k] = g_mi[f];
#pragma unroll
        for (int r = 0; r < ROWS; r++) rb[k][r] = 0.0f;
    }
    __syncthreads();

    const float4* s_sp4 = (const float4*)s_spec;   // row stride NG4
    const float4* s_dt4 = (const float4*)s_dt;
    const float4  melv  = ((const float4*)s_mel)[m * 2 + rg];

    for (int it = 0; it < ITERS; it++) {
        // ---- phase 1: gather (chunk x 8 rows, float4) ----
        float a[ROWS];
#pragma unroll
        for (int r = 0; r < ROWS; r++) a[r] = 0.0f;
        for (int j = 0; j < ngc; j++) {
            const float4 w = __ldg(&wg[j]);
            const int gg = g0 + j;
#pragma unroll
            for (int r = 0; r < ROWS; r++) {
                float4 x = s_sp4[r * NG4 + gg];
                a[r] = fmaf(w.w, x.w, fmaf(w.z, x.z, fmaf(w.y, x.y, fmaf(w.x, x.x, a[r]))));
            }
        }
        s_part[2 * tid]     = make_float4(a[0], a[1], a[2], a[3]);
        s_part[2 * tid + 1] = make_float4(a[4], a[5], a[6], a[7]);
        __syncthreads();

        // ---- phase 2: diff = mel - (chunk partial sums), transposed store ----
        {
            float4 e0 = s_part[c0];
            float4 e1 = s_part[c1];
            float4 d;
            d.x = melv.x - e0.x - e1.x;
            d.y = melv.y - e0.y - e1.y;
            d.z = melv.z - e0.z - e1.z;
            d.w = melv.w - e0.w - e1.w;
            ((float4*)s_dt)[m * 2 + rg] = d;
        }
        __syncthreads();

        // ---- phase 3: grad + momentum + clamp (broadcast diff float4s) ----
#pragma unroll
        for (int k = 0; k < 4; k++) {
            const int   f  = k * NTHREADS + tid;
            const int   mi = mir[k];
            const float w0 = w0r[k];
            const float w1 = w1r[k];
            const float4 dl0 = s_dt4[mi * 2];       // diff[mi]   rows 0-3
            const float4 dh0 = s_dt4[mi * 2 + 1];   // diff[mi]   rows 4-7
            const float4 dl1 = s_dt4[mi * 2 + 2];   // diff[mi+1] rows 0-3
            const float4 dh1 = s_dt4[mi * 2 + 3];   // diff[mi+1] rows 4-7
            float gg[ROWS];
            gg[0] = -c_INV * fmaf(dl0.x, w0, dl1.x * w1);
            gg[1] = -c_INV * fmaf(dl0.y, w0, dl1.y * w1);
            gg[2] = -c_INV * fmaf(dl0.z, w0, dl1.z * w1);
            gg[3] = -c_INV * fmaf(dl0.w, w0, dl1.w * w1);
            gg[4] = -c_INV * fmaf(dh0.x, w0, dh1.x * w1);
            gg[5] = -c_INV * fmaf(dh0.y, w0, dh1.y * w1);
            gg[6] = -c_INV * fmaf(dh0.z, w0, dh1.z * w1);
            gg[7] = -c_INV * fmaf(dh0.w, w0, dh1.w * w1);
#pragma unroll
            for (int r = 0; r < ROWS; r++) {
                float bv = fmaf(c_MOM, rb[k][r], gg[r]);
                rb[k][r] = bv;
                float sv = fmaxf(fmaf(-c_LR, bv, s_spec[r * NFP + f]), 0.0f);
                s_spec[r * NFP + f] = sv;
            }
        }
        __syncthreads();
    }

    // ---- output: out[b][f][t0..t0+7], two STG.128 per owned f ----
#pragma unroll
    for (int k = 0; k < 4; k++) {
        const int f = k * NTHREADS + tid;
        float4 v0 = make_float4(s_spec[0 * NFP + f], s_spec[1 * NFP + f],
                                s_spec[2 * NFP + f], s_spec[3 * NFP + f]);
        float4 v1 = make_float4(s_spec[4 * NFP + f], s_spec[5 * NFP + f],
                                s_spec[6 * NFP + f], s_spec[7 * NFP + f]);
        float4* p = (float4*)&out[((size_t)b * NF + f) * TT + t0];
        p[0] = v0;
        p[1] = v1;
    }
    // f = 1024: fb row identically zero -> spec stays at init (>= 0)
    if (tid < ROWS) {
        out[((size_t)b * NF + 1024) * TT + t0 + tid] =
            spec_init[(size_t)(row0 + tid) * NF + 1024];
    }
}

// ---------------------------------------------------------------------------
extern "C" void kernel_launch(void* const* d_in, const int* in_sizes, int n_in,
                              void* d_out, int out_size) {
    const float* melspec = nullptr;
    const float* spec_init = nullptr;
    const float* fb = nullptr;
    for (int i = 0; i < n_in; i++) {
        if (in_sizes[i] == NB * NM * TT)      melspec   = (const float*)d_in[i];
        else if (in_sizes[i] == NB * TT * NF) spec_init = (const float*)d_in[i];
        else if (in_sizes[i] == NF * NM)      fb        = (const float*)d_in[i];
    }
    float* out = (float*)d_out;

    const int smem_bytes = (ROWS * NFP) * 4 + NCH * 2 * 16 + 129 * 8 * 4 + NM * 8 * 4;

    cudaFuncSetAttribute(invmel_main, cudaFuncAttributeMaxDynamicSharedMemorySize,
                         smem_bytes);

    prep_all<<<1, NTHREADS>>>(fb);
    invmel_main<<<NBLOCKS, NTHREADS, smem_bytes>>>(melspec, spec_init, out);
}

// round 4
// speedup vs baseline: 1.7195x; 1.7195x over previous
#include <cuda_runtime.h>
#include <cstddef>

#define NF 1025      // n_stft
#define NM 128       // n_mels
#define NB 4         // batch
#define TT 1024      // time
#define ROWS 4       // (b,t) rows per CTA
#define NTHREADS 256
#define ITERS 20
#define NBLOCKS ((NB * TT) / ROWS)   // 1024
#define NGR 256      // granules: f = 4g+e, g<256; f=1024 handled separately
#define LISTCAP 1024
#define NDIFF 131    // diff[mel] for 0..127 + zero pads 128..130

__device__ float  g_w0[NF];
__device__ float  g_w1[NF];
__device__ int    g_mi[NF];
__device__ float4 g_wv[NGR * 4];        // [g][c] channel weight vectors
__device__ int    g_mb[NGR];            // base mel per granule
__device__ unsigned short g_list[LISTCAP];  // term idx = c*NGR + g, grouped by mel
__device__ int    g_redmeta[NM];        // start | count<<16

// ---------------------------------------------------------------------------
// Prep 1 (multi-block): per-freq sparse structure of fb.
// Each freq row has <=2 nonzeros at adjacent mels (mi, mi+1).
// ---------------------------------------------------------------------------
__global__ void prep_freq(const float* __restrict__ fb) {
    int f = blockIdx.x * blockDim.x + threadIdx.x;
    if (f >= NF) return;
    const float* row = fb + (size_t)f * NM;
    int mi = -1;
    for (int m = 0; m < NM; m++) if (row[m] > 0.0f) { mi = m; break; }
    float w0 = 0.0f, w1 = 0.0f;
    if (mi >= 0) {
        w0 = row[mi];
        w1 = (mi + 1 < NM) ? row[mi + 1] : 0.0f;
    } else mi = 0;
    g_mi[f] = mi; g_w0[f] = w0; g_w1[f] = w1;
}

// ---------------------------------------------------------------------------
// Prep 2 (single block, all loops <=256): per-granule 4-channel weight blocks
// + deterministic per-mel term lists for the reduction phase.
// ---------------------------------------------------------------------------
__global__ void prep_sched() {
    __shared__ int s_mb[NGR];
    __shared__ unsigned char s_nzm[NGR];
    __shared__ int s_cnt[NM];
    __shared__ int s_start[NM];
    const int t = threadIdx.x;

    // per-granule channel weights: channel c targets mel mb+c
    {
        const int g = t;
        const int mb = g_mi[4 * g];
        float wv[4][4];
#pragma unroll
        for (int c = 0; c < 4; c++)
#pragma unroll
            for (int e = 0; e < 4; e++) wv[c][e] = 0.0f;
#pragma unroll
        for (int e = 0; e < 4; e++) {
            int f = 4 * g + e;
            int c0 = g_mi[f] - mb;
            if (c0 < 0) c0 = 0;
            if (c0 > 2) c0 = 2;   // safety clamp (analysis: mi advances <=2 per granule)
            wv[c0][e]     += g_w0[f];
            wv[c0 + 1][e] += g_w1[f];
        }
        unsigned char nz = 0;
#pragma unroll
        for (int c = 0; c < 4; c++) {
            float4 v = make_float4(wv[c][0], wv[c][1], wv[c][2], wv[c][3]);
            g_wv[g * 4 + c] = v;
            if (v.x != 0.0f || v.y != 0.0f || v.z != 0.0f || v.w != 0.0f)
                nz |= (unsigned char)(1u << c);
        }
        s_mb[g] = mb;
        s_nzm[g] = nz;
        g_mb[g] = mb;
    }
    __syncthreads();

    // per-mel term counts
    if (t < NM) {
        int n = 0;
        for (int g = 0; g < NGR; g++) {
            int c = t - s_mb[g];
            if (c >= 0 && c < 4 && ((s_nzm[g] >> c) & 1)) n++;
        }
        s_cnt[t] = n;
    }
    __syncthreads();
    if (t == 0) {
        int acc = 0;
        for (int m = 0; m < NM; m++) { s_start[m] = acc; acc += s_cnt[m]; }
    }
    __syncthreads();
    if (t < NM) {
        int idx = s_start[t];
        g_redmeta[t] = s_start[t] | (s_cnt[t] << 16);
        for (int g = 0; g < NGR; g++) {   // g-ascending: deterministic sum order
            int c = t - s_mb[g];
            if (c >= 0 && c < 4 && ((s_nzm[g] >> c) & 1))
                g_list[idx++] = (unsigned short)(c * NGR + g);
        }
    }
}

// ---------------------------------------------------------------------------
// Main: 20 SGD iterations for 4 independent (b,t) rows per CTA.
// spec + momentum fully register-resident; smem only for mel-space
// partials (16 KB), diff (2.1 KB), term list (2 KB). 2 barriers/iter.
// ---------------------------------------------------------------------------
__global__ __launch_bounds__(NTHREADS, 3)
void invmel_main(const float* __restrict__ melspec,
                 const float* __restrict__ spec_init,
                 float* __restrict__ out) {
    __shared__ float4 s_p[4 * NGR];           // partials [c][g] x 4 rows
    __shared__ float4 s_diff[NDIFF];          // diff[mel] x 4 rows
    __shared__ unsigned short s_list[LISTCAP];

    const float cINV = 2.0f / (float)(NB * TT);
    const float cMOM = 0.9f;
    const float cLR  = 0.3f;

    const int tid  = threadIdx.x;
    const int row0 = blockIdx.x * ROWS;
    const int b    = row0 / TT;
    const int t0   = row0 % TT;

    // ---- register state: spec[e][r], momentum rb[e][r], weights wcv[c][e] ----
    float sp[4][4], rb[4][4], wcv[4][4];
#pragma unroll
    for (int r = 0; r < ROWS; r++)
#pragma unroll
        for (int e = 0; e < 4; e++) {
            sp[e][r] = spec_init[(size_t)(row0 + r) * NF + 4 * tid + e];
            rb[e][r] = 0.0f;
        }
    {
        float4 v0 = g_wv[tid * 4 + 0];
        float4 v1 = g_wv[tid * 4 + 1];
        float4 v2 = g_wv[tid * 4 + 2];
        float4 v3 = g_wv[tid * 4 + 3];
        wcv[0][0] = v0.x; wcv[0][1] = v0.y; wcv[0][2] = v0.z; wcv[0][3] = v0.w;
        wcv[1][0] = v1.x; wcv[1][1] = v1.y; wcv[1][2] = v1.z; wcv[1][3] = v1.w;
        wcv[2][0] = v2.x; wcv[2][1] = v2.y; wcv[2][2] = v2.z; wcv[2][3] = v2.w;
        wcv[3][0] = v3.x; wcv[3][1] = v3.y; wcv[3][2] = v3.z; wcv[3][3] = v3.w;
    }
    const int mb = g_mb[tid];

    // ---- reducer identity: lane pair (2k,2k+1) of warp w handles mel k*8+w ----
    const int lane = tid & 31;
    const int wrp  = tid >> 5;
    const int mel  = (lane >> 1) * 8 + wrp;    // balanced: every warp spans all sizes
    const bool evenlane = ((lane & 1) == 0);
    const int rm = g_redmeta[mel];
    const int rs = rm & 0xFFFF;
    const int rn = rm >> 16;
    const int h  = (rn + 1) >> 1;
    const int ts = evenlane ? rs : rs + h;
    const int te = evenlane ? rs + h : rs + rn;
    float4 melv = make_float4(0.f, 0.f, 0.f, 0.f);
    if (evenlane)
        melv = *(const float4*)&melspec[((size_t)b * NM + mel) * TT + t0];

    // ---- stage term list, zero diff pads ----
    for (int i = tid; i < LISTCAP; i += NTHREADS) s_list[i] = g_list[i];
    if (tid < NDIFF - NM) s_diff[NM + tid] = make_float4(0.f, 0.f, 0.f, 0.f);
    __syncthreads();

    for (int it = 0; it < ITERS; it++) {
        // ---- P1: per-granule channel partials (pure register FMA) ----
#pragma unroll
        for (int c = 0; c < 4; c++) {
            float a0, a1, a2, a3;
            a0 = wcv[c][0] * sp[0][0];
            a1 = wcv[c][0] * sp[0][1];
            a2 = wcv[c][0] * sp[0][2];
            a3 = wcv[c][0] * sp[0][3];
#pragma unroll
            for (int e = 1; e < 4; e++) {
                a0 = fmaf(wcv[c][e], sp[e][0], a0);
                a1 = fmaf(wcv[c][e], sp[e][1], a1);
                a2 = fmaf(wcv[c][e], sp[e][2], a2);
                a3 = fmaf(wcv[c][e], sp[e][3], a3);
            }
            s_p[c * NGR + tid] = make_float4(a0, a1, a2, a3);
        }
        __syncthreads();

        // ---- P2: mel-space reduction (lane-pair halves + shfl combine) ----
        float ax = 0.f, ay = 0.f, az = 0.f, aw = 0.f;
        for (int i = ts; i < te; i++) {
            float4 v = s_p[s_list[i]];
            ax += v.x; ay += v.y; az += v.z; aw += v.w;
        }
        ax += __shfl_xor_sync(0xFFFFFFFFu, ax, 1);
        ay += __shfl_xor_sync(0xFFFFFFFFu, ay, 1);
        az += __shfl_xor_sync(0xFFFFFFFFu, az, 1);
        aw += __shfl_xor_sync(0xFFFFFFFFu, aw, 1);
        if (evenlane) {
            s_diff[mel] = make_float4(melv.x - ax, melv.y - ay,
                                      melv.z - az, melv.w - aw);
        }
        __syncthreads();

        // ---- P3: grad + momentum + clamp, all in registers ----
        const float4 dA = s_diff[mb];
        const float4 dB = s_diff[mb + 1];
        const float4 dC = s_diff[mb + 2];
        const float4 dD = s_diff[mb + 3];
        const float dAr[4] = {dA.x, dA.y, dA.z, dA.w};
        const float dBr[4] = {dB.x, dB.y, dB.z, dB.w};
        const float dCr[4] = {dC.x, dC.y, dC.z, dC.w};
        const float dDr[4] = {dD.x, dD.y, dD.z, dD.w};
#pragma unroll
        for (int e = 0; e < 4; e++) {
#pragma unroll
            for (int r = 0; r < ROWS; r++) {
                float dd = wcv[0][e] * dAr[r];
                dd = fmaf(wcv[1][e], dBr[r], dd);
                dd = fmaf(wcv[2][e], dCr[r], dd);
                dd = fmaf(wcv[3][e], dDr[r], dd);
                float bv = fmaf(cMOM, rb[e][r], -cINV * dd);
                rb[e][r] = bv;
                sp[e][r] = fmaxf(fmaf(-cLR, bv, sp[e][r]), 0.0f);
            }
        }
        // no barrier needed here: next P1 writes s_p, whose last reads (P2)
        // happened before the barrier above; s_diff next written after it too.
    }

    // ---- output: out[b][4*tid+e][t0..t0+3], 4x STG.128 from registers ----
#pragma unroll
    for (int e = 0; e < 4; e++) {
        float4 v = make_float4(sp[e][0], sp[e][1], sp[e][2], sp[e][3]);
        *(float4*)&out[((size_t)b * NF + 4 * tid + e) * TT + t0] = v;
    }
    // f = 1024: fb row identically zero -> passthrough of init (>= 0)
    if (tid < ROWS) {
        out[((size_t)b * NF + 1024) * TT + t0 + tid] =
            spec_init[(size_t)(row0 + tid) * NF + 1024];
    }
}

// ---------------------------------------------------------------------------
extern "C" void kernel_launch(void* const* d_in, const int* in_sizes, int n_in,
                              void* d_out, int out_size) {
    const float* melspec = nullptr;
    const float* spec_init = nullptr;
    const float* fb = nullptr;
    for (int i = 0; i < n_in; i++) {
        if (in_sizes[i] == NB * NM * TT)      melspec   = (const float*)d_in[i];
        else if (in_sizes[i] == NB * TT * NF) spec_init = (const float*)d_in[i];
        else if (in_sizes[i] == NF * NM)      fb        = (const float*)d_in[i];
    }
    float* out = (float*)d_out;

    prep_freq<<<(NF + 255) / 256, 256>>>(fb);
    prep_sched<<<1, NTHREADS>>>();
    invmel_main<<<NBLOCKS, NTHREADS>>>(melspec, spec_init, out);
}

// round 5
// speedup vs baseline: 1.9063x; 1.1087x over previous
#include <cuda_runtime.h>
#include <cstddef>

#define NF 1025      // n_stft
#define NM 128       // n_mels
#define NB 4         // batch
#define TT 1024      // time
#define ROWS 4       // (b,t) rows per CTA
#define NTHREADS 256
#define ITERS 20
#define NBLOCKS ((NB * TT) / ROWS)   // 1024
#define NGR 256      // granules: f = 4g+e, g<256; f=1024 handled separately
#define LISTCAP 1024
#define NDIFF 131    // diff[mel] 0..127 + zero pads

typedef unsigned long long u64;

#define F2FMA(d,a,b,c) asm("fma.rn.f32x2 %0, %1, %2, %3;" : "=l"(d) : "l"(a), "l"(b), "l"(c))
#define F2MUL(d,a,b)   asm("mul.rn.f32x2 %0, %1, %2;"     : "=l"(d) : "l"(a), "l"(b))
#define F2ADD(d,a,b)   asm("add.rn.f32x2 %0, %1, %2;"     : "=l"(d) : "l"(a), "l"(b))
#define PK2(d,lo,hi)   asm("mov.b64 %0, {%1, %2};" : "=l"(d) : "f"(lo), "f"(hi))
#define UPK2(lo,hi,s)  asm("mov.b64 {%0, %1}, %2;" : "=f"(lo), "=f"(hi) : "l"(s))

__device__ float  g_w0[NF];
__device__ float  g_w1[NF];
__device__ int    g_mi[NF];
__device__ float4 g_wv[NGR * 4];        // [g][c] channel weight vectors
__device__ int    g_mb[NGR];            // base mel per granule
__device__ unsigned short g_list[LISTCAP];  // term idx = c*NGR + g, per mel
__device__ int    g_redmeta[NM];        // start | count<<16

// ---------------------------------------------------------------------------
// Prep 1: per-freq sparse structure. Chunked float4 loads, no early break
// (keeps MLP ~8 so DRAM latency is overlapped).
// ---------------------------------------------------------------------------
__global__ void prep_freq(const float* __restrict__ fb) {
    int f = blockIdx.x * blockDim.x + threadIdx.x;
    if (f >= NF) return;
    const float4* r4 = (const float4*)(fb + (size_t)f * NM);
    int mi = -1;
#pragma unroll
    for (int q8 = 0; q8 < 4; q8++) {
        float4 v[8];
#pragma unroll
        for (int j = 0; j < 8; j++) v[j] = r4[q8 * 8 + j];
#pragma unroll
        for (int j = 0; j < 8; j++) {
            int base = (q8 * 8 + j) * 4;
            if (mi < 0) {
                if      (v[j].x > 0.0f) mi = base;
                else if (v[j].y > 0.0f) mi = base + 1;
                else if (v[j].z > 0.0f) mi = base + 2;
                else if (v[j].w > 0.0f) mi = base + 3;
            }
        }
    }
    float w0 = 0.0f, w1 = 0.0f;
    if (mi >= 0) {
        const float* row = fb + (size_t)f * NM;
        w0 = row[mi];
        w1 = (mi + 1 < NM) ? row[mi + 1] : 0.0f;
    } else mi = 0;
    g_mi[f] = mi; g_w0[f] = w0; g_w1[f] = w1;
}

// ---------------------------------------------------------------------------
// Prep 2 (single block): per-granule 4-channel weight blocks + deterministic
// per-mel term lists for the reduction phase. (Validated in R4.)
// ---------------------------------------------------------------------------
__global__ void prep_sched() {
    __shared__ int s_mb[NGR];
    __shared__ unsigned char s_nzm[NGR];
    __shared__ int s_cnt[NM];
    __shared__ int s_start[NM];
    const int t = threadIdx.x;

    {
        const int g = t;
        const int mb = g_mi[4 * g];
        float wv[4][4];
#pragma unroll
        for (int c = 0; c < 4; c++)
#pragma unroll
            for (int e = 0; e < 4; e++) wv[c][e] = 0.0f;
#pragma unroll
        for (int e = 0; e < 4; e++) {
            int f = 4 * g + e;
            int c0 = g_mi[f] - mb;
            if (c0 < 0) c0 = 0;
            if (c0 > 2) c0 = 2;
            wv[c0][e]     += g_w0[f];
            wv[c0 + 1][e] += g_w1[f];
        }
        unsigned char nz = 0;
#pragma unroll
        for (int c = 0; c < 4; c++) {
            float4 v = make_float4(wv[c][0], wv[c][1], wv[c][2], wv[c][3]);
            g_wv[g * 4 + c] = v;
            if (v.x != 0.0f || v.y != 0.0f || v.z != 0.0f || v.w != 0.0f)
                nz |= (unsigned char)(1u << c);
        }
        s_mb[g] = mb;
        s_nzm[g] = nz;
        g_mb[g] = mb;
    }
    __syncthreads();

    if (t < NM) {
        int n = 0;
        for (int g = 0; g < NGR; g++) {
            int c = t - s_mb[g];
            if (c >= 0 && c < 4 && ((s_nzm[g] >> c) & 1)) n++;
        }
        s_cnt[t] = n;
    }
    __syncthreads();
    if (t == 0) {
        int acc = 0;
        for (int m = 0; m < NM; m++) { s_start[m] = acc; acc += s_cnt[m]; }
    }
    __syncthreads();
    if (t < NM) {
        int idx = s_start[t];
        g_redmeta[t] = s_start[t] | (s_cnt[t] << 16);
        for (int g = 0; g < NGR; g++) {   // g-ascending: deterministic sum order
            int c = t - s_mb[g];
            if (c >= 0 && c < 4 && ((s_nzm[g] >> c) & 1))
                g_list[idx++] = (unsigned short)(c * NGR + g);
        }
    }
}

// ---------------------------------------------------------------------------
// Main: 20 SGD iterations, 4 rows per CTA. All row-state in packed f32x2
// register pairs; fma.rn.f32x2 halves the fma-pipe instruction stream.
// ---------------------------------------------------------------------------
__global__ __launch_bounds__(NTHREADS, 3)
void invmel_main(const float* __restrict__ melspec,
                 const float* __restrict__ spec_init,
                 float* __restrict__ out) {
    __shared__ float4 s_p[4 * NGR];           // partials [c][g] x 4 rows
    __shared__ float4 s_diff[NDIFF];          // diff[mel] x 4 rows
    __shared__ unsigned short s_list[LISTCAP];

    const float cINV = 2.0f / (float)(NB * TT);

    const int tid  = threadIdx.x;
    const int row0 = blockIdx.x * ROWS;
    const int b    = row0 / TT;
    const int t0   = row0 % TT;

    // ---- packed weights: wpk[c][e] = (w, w) ----
    u64 wpk[4][4];
#pragma unroll
    for (int c = 0; c < 4; c++) {
        float4 v = g_wv[tid * 4 + c];
        PK2(wpk[c][0], v.x, v.x);
        PK2(wpk[c][1], v.y, v.y);
        PK2(wpk[c][2], v.z, v.z);
        PK2(wpk[c][3], v.w, v.w);
    }
    const int mb = g_mb[tid];

    // ---- packed row state: (r0,r1) and (r2,r3) pairs ----
    u64 sp01[4], sp23[4], rb01[4], rb23[4];
#pragma unroll
    for (int e = 0; e < 4; e++) {
        float v0 = spec_init[(size_t)(row0 + 0) * NF + 4 * tid + e];
        float v1 = spec_init[(size_t)(row0 + 1) * NF + 4 * tid + e];
        float v2 = spec_init[(size_t)(row0 + 2) * NF + 4 * tid + e];
        float v3 = spec_init[(size_t)(row0 + 3) * NF + 4 * tid + e];
        PK2(sp01[e], v0, v1);
        PK2(sp23[e], v2, v3);
        rb01[e] = 0ull;
        rb23[e] = 0ull;
    }
    u64 kMOM, kNINV, kNLR;
    PK2(kMOM, 0.9f, 0.9f);
    PK2(kNINV, -cINV, -cINV);
    PK2(kNLR, -0.3f, -0.3f);

    // ---- reducer identity: lane pair (2k,2k+1) of warp w -> mel k*8+w ----
    const int lane = tid & 31;
    const int wrp  = tid >> 5;
    const int mel  = (lane >> 1) * 8 + wrp;
    const bool evenlane = ((lane & 1) == 0);
    const int rm = g_redmeta[mel];
    const int rs = rm & 0xFFFF;
    const int rn = rm >> 16;
    const int h  = (rn + 1) >> 1;
    const int ts = evenlane ? rs : rs + h;
    const int te = evenlane ? rs + h : rs + rn;
    const float4* melp = (const float4*)&melspec[((size_t)b * NM + mel) * TT + t0];

    // ---- stage term list, zero diff pads ----
    for (int i = tid; i < LISTCAP; i += NTHREADS) s_list[i] = g_list[i];
    if (tid < NDIFF - NM) s_diff[NM + tid] = make_float4(0.f, 0.f, 0.f, 0.f);
    __syncthreads();

    for (int it = 0; it < ITERS; it++) {
        // ---- P1: per-granule channel partials (packed FMA) ----
#pragma unroll
        for (int c = 0; c < 4; c++) {
            u64 a01, a23;
            F2MUL(a01, wpk[c][0], sp01[0]);
            F2MUL(a23, wpk[c][0], sp23[0]);
#pragma unroll
            for (int e = 1; e < 4; e++) {
                F2FMA(a01, wpk[c][e], sp01[e], a01);
                F2FMA(a23, wpk[c][e], sp23[e], a23);
            }
            ulonglong2 stv; stv.x = a01; stv.y = a23;
            *(ulonglong2*)&s_p[c * NGR + tid] = stv;
        }
        __syncthreads();

        // ---- P2: mel-space reduction (packed adds + shfl combine) ----
        u64 acc01 = 0ull, acc23 = 0ull;   // bits of (0.0f, 0.0f)
        for (int i = ts; i < te; i++) {
            ulonglong2 v = *(const ulonglong2*)&s_p[s_list[i]];
            F2ADD(acc01, acc01, v.x);
            F2ADD(acc23, acc23, v.y);
        }
        float ax, ay, az, aw;
        UPK2(ax, ay, acc01);
        UPK2(az, aw, acc23);
        ax += __shfl_xor_sync(0xFFFFFFFFu, ax, 1);
        ay += __shfl_xor_sync(0xFFFFFFFFu, ay, 1);
        az += __shfl_xor_sync(0xFFFFFFFFu, az, 1);
        aw += __shfl_xor_sync(0xFFFFFFFFu, aw, 1);
        if (evenlane) {
            float4 mv = *melp;  // L1-resident after iter 0
            s_diff[mel] = make_float4(mv.x - ax, mv.y - ay, mv.z - az, mv.w - aw);
        }
        __syncthreads();

        // ---- P3: grad + momentum + clamp (packed; clamp scalar) ----
        ulonglong2 d0 = *(const ulonglong2*)&s_diff[mb + 0];
        ulonglong2 d1 = *(const ulonglong2*)&s_diff[mb + 1];
        ulonglong2 d2 = *(const ulonglong2*)&s_diff[mb + 2];
        ulonglong2 d3 = *(const ulonglong2*)&s_diff[mb + 3];
#pragma unroll
        for (int e = 0; e < 4; e++) {
            u64 g01, g23;
            F2MUL(g01, wpk[0][e], d0.x);
            F2MUL(g23, wpk[0][e], d0.y);
            F2FMA(g01, wpk[1][e], d1.x, g01);
            F2FMA(g23, wpk[1][e], d1.y, g23);
            F2FMA(g01, wpk[2][e], d2.x, g01);
            F2FMA(g23, wpk[2][e], d2.y, g23);
            F2FMA(g01, wpk[3][e], d3.x, g01);
            F2FMA(g23, wpk[3][e], d3.y, g23);
            u64 t01, t23;
            F2MUL(t01, kNINV, g01);
            F2MUL(t23, kNINV, g23);
            F2FMA(rb01[e], kMOM, rb01[e], t01);
            F2FMA(rb23[e], kMOM, rb23[e], t23);
            u64 s01, s23;
            F2FMA(s01, kNLR, rb01[e], sp01[e]);
            F2FMA(s23, kNLR, rb23[e], sp23[e]);
            float lo, hi;
            UPK2(lo, hi, s01);
            PK2(sp01[e], fmaxf(lo, 0.0f), fmaxf(hi, 0.0f));
            UPK2(lo, hi, s23);
            PK2(sp23[e], fmaxf(lo, 0.0f), fmaxf(hi, 0.0f));
        }
        // no barrier here: next P1 writes s_p (last read before barrier 2);
        // s_diff next written only after barrier 1 of the next iteration.
    }

    // ---- output: out[b][4*tid+e][t0..t0+3] as one 16B store each ----
#pragma unroll
    for (int e = 0; e < 4; e++) {
        ulonglong2 v; v.x = sp01[e]; v.y = sp23[e];   // rows 0,1,2,3
        *(ulonglong2*)&out[((size_t)b * NF + 4 * tid + e) * TT + t0] = v;
    }
    // f = 1024: fb row identically zero -> passthrough of init (>= 0)
    if (tid < ROWS) {
        out[((size_t)b * NF + 1024) * TT + t0 + tid] =
            spec_init[(size_t)(row0 + tid) * NF + 1024];
    }
}

// ---------------------------------------------------------------------------
extern "C" void kernel_launch(void* const* d_in, const int* in_sizes, int n_in,
                              void* d_out, int out_size) {
    const float* melspec = nullptr;
    const float* spec_init = nullptr;
    const float* fb = nullptr;
    for (int i = 0; i < n_in; i++) {
        if (in_sizes[i] == NB * NM * TT)      melspec   = (const float*)d_in[i];
        else if (in_sizes[i] == NB * TT * NF) spec_init = (const float*)d_in[i];
        else if (in_sizes[i] == NF * NM)      fb        = (const float*)d_in[i];
    }
    float* out = (float*)d_out;

    prep_freq<<<(NF + 255) / 256, 256>>>(fb);
    prep_sched<<<1, NTHREADS>>>();
    invmel_main<<<NBLOCKS, NTHREADS>>>(melspec, spec_init, out);
}